// round 1
// baseline (speedup 1.0000x reference)
#include <cuda_runtime.h>
#include <math.h>

#define NQ 8
#define NS 256          // 2^8 amplitudes
#define DEPTH 200
#define BSZ 16384
#define NXF 64
#define NT 32           // batches per block in main kernel
#define NTP 33          // padded batch stride in shared
#define NBLK (BSZ/NT)   // 512 blocks

// ---------------- device globals (no cudaMalloc allowed) ----------------
__device__ float4 g_uv[600 * 8];     // per layer, per qubit: (u.re,u.im,v.re,v.im) of RY(b)*RX(a)
__device__ float2 g_encphi[128];     // (cos(phi/2), sin(phi/2)) for the 2*64 encode phi angles
__device__ float2 g_v0[NS];          // U1 |0>
__device__ float2 g_U2T[NS * NS];    // [k][m] = (U2*Dcz)[m][k]
__device__ float2 g_U3T[NS * NS];    // [k][m] = (U3*Dcz)[m][k]

// ring-CZ parity sign for amplitude index n (qubit i <-> bit 7-i)
__device__ __forceinline__ float czsign(int n) {
    int par = __popc(n & (n >> 1)) + ((n & (n >> 7)) & 1);
    return (par & 1) ? -1.0f : 1.0f;
}

// ---------------- K0: angle tables ----------------
__global__ void k_tables(const float* __restrict__ phi) {
    int tid = threadIdx.x;
    // fused layer gates: M = RY(b)*RX(a) = [[u, -conj(v)],[v, conj(u)]]
    // u = (ca*cb, sa*sb), v = (ca*sb, -sa*cb)
    for (int idx = tid; idx < 600 * 8; idx += blockDim.x) {
        int L = idx >> 3, q = idx & 7;
        int base, l;
        if (L < 200)      { base = 0;    l = L; }
        else if (L < 400) { base = 3264; l = L - 200; }
        else              { base = 6528; l = L - 400; }
        float a = phi[base + l * 16 + q];
        float b = phi[base + l * 16 + 8 + q];
        float ca, sa, cb, sb;
        sincosf(0.5f * a, &sa, &ca);
        sincosf(0.5f * b, &sb, &cb);
        g_uv[idx] = make_float4(ca * cb, sa * sb, ca * sb, -sa * cb);
    }
    for (int idx = tid; idx < 128; idx += blockDim.x) {
        // idx<64 : phi[3200+idx] ; idx>=64 : phi[6464+(idx-64)] = phi[6400+idx]
        int base = (idx < 64) ? 3200 : 6400;
        float p = phi[base + idx];
        float c, s;
        sincosf(0.5f * p, &s, &c);
        g_encphi[idx] = make_float2(c, s);
    }
}

// ---------------- K1: build v0, U2', U3' columns ----------------
// blocks 0..255  : column c of U2' = (U2 * Dcz)  (init e_c * czsign(c), 200 CZ layers of p2)
// blocks 256..511: column c of U3' = (U3 * Dcz)  (199 CZ layers + final layer w/o CZ, of p3)
// block  512     : v0 = U1 |0>                    (200 CZ layers of p1)
__global__ void __launch_bounds__(128) k_build() {
    __shared__ float2 st[NS];
    int t = threadIdx.x;           // 0..127
    int blk = blockIdx.x;

    int Lbase, col;
    bool lastCZ;
    float2* outp;
    float initv;
    if (blk < 256)      { Lbase = 200; lastCZ = true;  col = blk;       outp = &g_U2T[col * NS]; initv = czsign(col); }
    else if (blk < 512) { Lbase = 400; lastCZ = false; col = blk - 256; outp = &g_U3T[col * NS]; initv = czsign(col); }
    else                { Lbase = 0;   lastCZ = true;  col = 0;         outp = g_v0;             initv = 1.0f; }

    st[t]       = make_float2(0.f, 0.f);
    st[t + 128] = make_float2(0.f, 0.f);
    __syncthreads();
    if (t == 0) st[col] = make_float2(initv, 0.f);

    float s0 = czsign(2 * t);       // for n = 2t   (owned after q==7 gate)
    float s1 = czsign(2 * t + 1);   // for n = 2t+1
    __syncthreads();

    for (int l = 0; l < DEPTH; l++) {
        bool cz = (l < DEPTH - 1) || lastCZ;
        #pragma unroll
        for (int q = 0; q < 8; q++) {
            float4 uv = g_uv[(Lbase + l) * 8 + q];
            int p = 7 - q;
            int low = (1 << p) - 1;
            int n0 = ((t & ~low) << 1) | (t & low);
            int n1 = n0 | (1 << p);
            float2 a0 = st[n0], a1 = st[n1];
            float2 b0, b1;
            // new0 = u*a0 - conj(v)*a1 ; new1 = v*a0 + conj(u)*a1
            b0.x = uv.x * a0.x - uv.y * a0.y - (uv.z * a1.x + uv.w * a1.y);
            b0.y = uv.x * a0.y + uv.y * a0.x - (uv.z * a1.y - uv.w * a1.x);
            b1.x = uv.z * a0.x - uv.w * a0.y + (uv.x * a1.x + uv.y * a1.y);
            b1.y = uv.z * a0.y + uv.w * a0.x + (uv.x * a1.y - uv.y * a1.x);
            if (q == 7 && cz) {   // fold CZ into last gate of layer (n0=2t, n1=2t+1)
                b0.x *= s0; b0.y *= s0;
                b1.x *= s1; b1.y *= s1;
            }
            st[n0] = b0; st[n1] = b1;
            __syncthreads();
        }
    }
    outp[t] = st[t];
    outp[t + 128] = st[t + 128];
}

// ---------------- K2: fused per-batch pipeline ----------------
// SU(2) compose: new = g * E, where M=[[u,-conj(v)],[v,conj(u)]]
__device__ __forceinline__ void su2_mul(float& Eur, float& Eui, float& Evr, float& Evi,
                                        float gur, float gui, float gvr, float gvi) {
    float ur = gur * Eur - gui * Eui - (gvr * Evr + gvi * Evi);
    float ui = gur * Eui + gui * Eur - (gvr * Evi - gvi * Evr);
    float vr = gvr * Eur - gvi * Eui + (gur * Evr + gui * Evi);
    float vi = gvr * Eui + gvi * Eur + (gur * Evi - gui * Evr);
    Eur = ur; Eui = ui; Evr = vr; Evi = vi;
}

// compose 12 rotations for (batch, qubit i) into one SU(2) (u,v)
__device__ __forceinline__ float4 compose_E(const float* __restrict__ x, int bg,
                                            int xoff, int enc, int i) {
    float Eur = 1.f, Eui = 0.f, Evr = 0.f, Evi = 0.f;
    #pragma unroll
    for (int j = 0; j < 4; j++) {
        float2 p0 = g_encphi[enc * 64 + 8 * i + 2 * j];
        float2 p1 = g_encphi[enc * 64 + 8 * i + 2 * j + 1];
        float xv = x[(size_t)bg * NXF + xoff + 4 * i + j];
        float sx, cx;
        sincosf(0.5f * xv, &sx, &cx);
        if ((j & 1) == 0) {
            su2_mul(Eur, Eui, Evr, Evi, p0.x, 0.f, p0.y, 0.f);   // RY(p0)
            su2_mul(Eur, Eui, Evr, Evi, cx, 0.f, 0.f, -sx);      // RX(x)
            su2_mul(Eur, Eui, Evr, Evi, p1.x, 0.f, p1.y, 0.f);   // RY(p1)
        } else {
            su2_mul(Eur, Eui, Evr, Evi, p0.x, 0.f, 0.f, -p0.y);  // RX(p0)
            su2_mul(Eur, Eui, Evr, Evi, cx, 0.f, sx, 0.f);       // RY(x)
            su2_mul(Eur, Eui, Evr, Evi, p1.x, 0.f, 0.f, -p1.y);  // RX(p1)
        }
    }
    return make_float4(Eur, Eui, Evr, Evi);
}

// apply 8 per-batch single-qubit gates (tensor product) to sPsi [amp*NTP + b]
__device__ __forceinline__ void apply_gates(float2* sPsi, const float4* sE, int tid) {
    #pragma unroll
    for (int q = 0; q < 8; q++) {
        int p = 7 - q;
        int low = (1 << p) - 1;
        #pragma unroll
        for (int it = 0; it < (128 * NT) / 256; it++) {  // 16
            int task = tid + it * 256;
            int b = task & (NT - 1);
            int pr = task >> 5;
            int n0 = ((pr & ~low) << 1) | (pr & low);
            int n1 = n0 | (1 << p);
            float4 E = sE[q * NT + b];
            float2 a0 = sPsi[n0 * NTP + b];
            float2 a1 = sPsi[n1 * NTP + b];
            float2 b0, b1;
            b0.x = E.x * a0.x - E.y * a0.y - (E.z * a1.x + E.w * a1.y);
            b0.y = E.x * a0.y + E.y * a0.x - (E.z * a1.y - E.w * a1.x);
            b1.x = E.z * a0.x - E.w * a0.y + (E.x * a1.x + E.y * a1.y);
            b1.y = E.z * a0.y + E.w * a0.x + (E.x * a1.y - E.y * a1.x);
            sPsi[n0 * NTP + b] = b0;
            sPsi[n1 * NTP + b] = b1;
        }
        __syncthreads();
    }
}

// in-place complex GEMM: sPsi[m][b] = sum_k AT[k][m] * sPsi[k][b]
__device__ __forceinline__ void do_gemm(float2* sPsi, float2* sA,
                                        const float2* __restrict__ AT,
                                        int tid, int lane, int warp) {
    float accr[8][4], acci[8][4];
    #pragma unroll
    for (int r = 0; r < 8; r++)
        #pragma unroll
        for (int j = 0; j < 4; j++) { accr[r][j] = 0.f; acci[r][j] = 0.f; }

    for (int kc = 0; kc < 32; kc++) {
        __syncthreads();  // sA reuse safe
        #pragma unroll
        for (int r = 0; r < 8; r++) {
            int idx = tid + r * 256;
            sA[idx] = AT[kc * 2048 + idx];
        }
        __syncthreads();
        #pragma unroll
        for (int kk = 0; kk < 8; kk++) {
            int k = kc * 8 + kk;
            float2 Bv[4];
            #pragma unroll
            for (int j = 0; j < 4; j++) Bv[j] = sPsi[k * NTP + warp * 4 + j];
            #pragma unroll
            for (int r = 0; r < 8; r++) {
                float2 Av = sA[kk * 256 + lane + 32 * r];
                #pragma unroll
                for (int j = 0; j < 4; j++) {
                    accr[r][j] += Av.x * Bv[j].x - Av.y * Bv[j].y;
                    acci[r][j] += Av.x * Bv[j].y + Av.y * Bv[j].x;
                }
            }
        }
    }
    __syncthreads();  // all reads of sPsi done before overwrite
    #pragma unroll
    for (int r = 0; r < 8; r++)
        #pragma unroll
        for (int j = 0; j < 4; j++)
            sPsi[(lane + 32 * r) * NTP + warp * 4 + j] = make_float2(accr[r][j], acci[r][j]);
    __syncthreads();
}

__global__ void __launch_bounds__(256) k_main(const float* __restrict__ x,
                                              float* __restrict__ out) {
    extern __shared__ float smraw[];
    float2* sPsi = (float2*)smraw;            // NS * NTP
    float2* sA   = sPsi + NS * NTP;           // 8 * 256
    float4* sE   = (float4*)(sA + 8 * NS);    // 8 * NT

    int tid = threadIdx.x;
    int lane = tid & 31, warp = tid >> 5;     // 8 warps
    int bbase = blockIdx.x * NT;

    // ---- E1 compose: tid -> (b = tid&31, i = tid>>5) ----
    {
        int b = tid & (NT - 1), i = tid >> 5;
        sE[i * NT + b] = compose_E(x, bbase + b, 0, 0, i);
    }
    // ---- init Psi = v0 (broadcast over batches) ----
    for (int idx = tid; idx < NS * NT; idx += 256) {
        int b = idx & (NT - 1), amp = idx >> 5;
        sPsi[amp * NTP + b] = g_v0[amp];
    }
    __syncthreads();

    apply_gates(sPsi, sE, tid);               // encode 1 (CZ folded into U2')
    do_gemm(sPsi, sA, g_U2T, tid, lane, warp);

    // ---- E2 compose ----
    {
        int b = tid & (NT - 1), i = tid >> 5;
        sE[i * NT + b] = compose_E(x, bbase + b, 32, 1, i);
    }
    __syncthreads();

    apply_gates(sPsi, sE, tid);               // encode 2 (CZ folded into U3')
    do_gemm(sPsi, sA, g_U3T, tid, lane, warp);

    // ---- measurement: warp w handles batches w*4..w*4+3 ----
    for (int j = 0; j < 4; j++) {
        int b = warp * 4 + j;
        float sums[8];
        #pragma unroll
        for (int k = 0; k < 8; k++) sums[k] = 0.f;
        #pragma unroll
        for (int r = 0; r < 8; r++) {
            int m = lane + 32 * r;
            float2 ps = sPsi[m * NTP + b];
            float p2 = ps.x * ps.x + ps.y * ps.y;
            sums[4] += (m & 128) ? -p2 : p2;   // Z q0
            sums[5] += (m & 64)  ? -p2 : p2;   // Z q1
            sums[6] += (m & 32)  ? -p2 : p2;   // Z q2
            sums[7] += (m & 16)  ? -p2 : p2;   // Z q3
            float2 q0 = sPsi[(m ^ 128) * NTP + b];
            sums[0] += ps.x * q0.x + ps.y * q0.y;   // X q0
            float2 q1 = sPsi[(m ^ 64) * NTP + b];
            sums[1] += ps.x * q1.x + ps.y * q1.y;   // X q1
            float2 q2 = sPsi[(m ^ 32) * NTP + b];
            sums[2] += ps.x * q2.x + ps.y * q2.y;   // X q2
            float2 q3 = sPsi[(m ^ 16) * NTP + b];
            sums[3] += ps.x * q3.x + ps.y * q3.y;   // X q3
        }
        #pragma unroll
        for (int off = 16; off; off >>= 1) {
            #pragma unroll
            for (int k = 0; k < 8; k++)
                sums[k] += __shfl_xor_sync(0xffffffffu, sums[k], off);
        }
        if (lane < 8) out[(size_t)(bbase + b) * 8 + lane] = sums[lane];
    }
}

// ---------------- launch ----------------
extern "C" void kernel_launch(void* const* d_in, const int* in_sizes, int n_in,
                              void* d_out, int out_size) {
    const float* x   = (const float*)d_in[0];
    const float* phi = (const float*)d_in[1];
    float* out = (float*)d_out;

    const size_t smem = (size_t)(NS * NTP) * sizeof(float2)   // 67584
                      + (size_t)(8 * NS) * sizeof(float2)     // 16384
                      + (size_t)(8 * NT) * sizeof(float4);    //  4096
    cudaFuncSetAttribute(k_main, cudaFuncAttributeMaxDynamicSharedMemorySize, (int)smem);

    k_tables<<<1, 256>>>(phi);
    k_build<<<513, 128>>>();
    k_main<<<NBLK, 256, smem>>>(x, out);
}

// round 2
// speedup vs baseline: 1.3006x; 1.3006x over previous
#include <cuda_runtime.h>
#include <math.h>

#define NQ 8
#define NS 256          // 2^8 amplitudes
#define DEPTH 200
#define BSZ 16384
#define NXF 64
#define NT 32           // batches per block in main kernel
#define NTP 33          // padded batch stride in shared
#define NBLK (BSZ/NT)   // 512 blocks

typedef unsigned long long ull;

// ---------------- device globals (no cudaMalloc allowed) ----------------
__device__ float4 g_uv[600 * 8];     // per layer, per qubit: (u.re,u.im,v.re,v.im) of RY(b)*RX(a)
__device__ float2 g_encphi[128];     // (cos(phi/2), sin(phi/2)) for the 2*64 encode phi angles
__device__ float2 g_v0[NS];          // U1 |0>
__device__ float2 g_U2T[NS * NS];    // [k][m] = (U2*Dcz)[m][k]
__device__ float2 g_U3T[NS * NS];    // [k][m] = (U3*Dcz)[m][k]

// ---------------- packed f32x2 helpers (Blackwell FFMA2 path) ----------------
__device__ __forceinline__ void ffma2(ull& d, ull a, ull b) {
    asm("fma.rn.f32x2 %0, %1, %2, %0;" : "+l"(d) : "l"(a), "l"(b));
}
__device__ __forceinline__ ull pack2(float lo, float hi) {
    ull r; asm("mov.b64 %0, {%1, %2};" : "=l"(r) : "f"(lo), "f"(hi)); return r;
}

// ring-CZ parity sign for amplitude index n (qubit i <-> bit 7-i)
__device__ __forceinline__ float czsign(int n) {
    int par = __popc(n & (n >> 1)) + ((n & (n >> 7)) & 1);
    return (par & 1) ? -1.0f : 1.0f;
}

// ---------------- K0: angle tables ----------------
__global__ void k_tables(const float* __restrict__ phi) {
    int tid = threadIdx.x;
    for (int idx = tid; idx < 600 * 8; idx += blockDim.x) {
        int L = idx >> 3, q = idx & 7;
        int base, l;
        if (L < 200)      { base = 0;    l = L; }
        else if (L < 400) { base = 3264; l = L - 200; }
        else              { base = 6528; l = L - 400; }
        float a = phi[base + l * 16 + q];
        float b = phi[base + l * 16 + 8 + q];
        float ca, sa, cb, sb;
        sincosf(0.5f * a, &sa, &ca);
        sincosf(0.5f * b, &sb, &cb);
        g_uv[idx] = make_float4(ca * cb, sa * sb, ca * sb, -sa * cb);
    }
    for (int idx = tid; idx < 128; idx += blockDim.x) {
        int base = (idx < 64) ? 3200 : 6400;
        float p = phi[base + idx];
        float c, s;
        sincosf(0.5f * p, &s, &c);
        g_encphi[idx] = make_float2(c, s);
    }
}

// ---------------- K1: build v0, U2', U3' columns ----------------
__global__ void __launch_bounds__(128) k_build() {
    __shared__ float2 st[NS];
    int t = threadIdx.x;           // 0..127
    int blk = blockIdx.x;

    int Lbase, col;
    bool lastCZ;
    float2* outp;
    float initv;
    if (blk < 256)      { Lbase = 200; lastCZ = true;  col = blk;       outp = &g_U2T[col * NS]; initv = czsign(col); }
    else if (blk < 512) { Lbase = 400; lastCZ = false; col = blk - 256; outp = &g_U3T[col * NS]; initv = czsign(col); }
    else                { Lbase = 0;   lastCZ = true;  col = 0;         outp = g_v0;             initv = 1.0f; }

    st[t]       = make_float2(0.f, 0.f);
    st[t + 128] = make_float2(0.f, 0.f);
    __syncthreads();
    if (t == 0) st[col] = make_float2(initv, 0.f);

    float s0 = czsign(2 * t);
    float s1 = czsign(2 * t + 1);
    __syncthreads();

    for (int l = 0; l < DEPTH; l++) {
        bool cz = (l < DEPTH - 1) || lastCZ;
        #pragma unroll
        for (int q = 0; q < 8; q++) {
            float4 uv = g_uv[(Lbase + l) * 8 + q];
            int p = 7 - q;
            int low = (1 << p) - 1;
            int n0 = ((t & ~low) << 1) | (t & low);
            int n1 = n0 | (1 << p);
            float2 a0 = st[n0], a1 = st[n1];
            float2 b0, b1;
            b0.x = uv.x * a0.x - uv.y * a0.y - (uv.z * a1.x + uv.w * a1.y);
            b0.y = uv.x * a0.y + uv.y * a0.x - (uv.z * a1.y - uv.w * a1.x);
            b1.x = uv.z * a0.x - uv.w * a0.y + (uv.x * a1.x + uv.y * a1.y);
            b1.y = uv.z * a0.y + uv.w * a0.x + (uv.x * a1.y - uv.y * a1.x);
            if (q == 7 && cz) {
                b0.x *= s0; b0.y *= s0;
                b1.x *= s1; b1.y *= s1;
            }
            st[n0] = b0; st[n1] = b1;
            __syncthreads();
        }
    }
    outp[t] = st[t];
    outp[t + 128] = st[t + 128];
}

// ---------------- K2: fused per-batch pipeline ----------------
__device__ __forceinline__ void su2_mul(float& Eur, float& Eui, float& Evr, float& Evi,
                                        float gur, float gui, float gvr, float gvi) {
    float ur = gur * Eur - gui * Eui - (gvr * Evr + gvi * Evi);
    float ui = gur * Eui + gui * Eur - (gvr * Evi - gvi * Evr);
    float vr = gvr * Eur - gvi * Eui + (gur * Evr + gui * Evi);
    float vi = gvr * Eui + gvi * Eur + (gur * Evi - gui * Evr);
    Eur = ur; Eui = ui; Evr = vr; Evi = vi;
}

__device__ __forceinline__ float4 compose_E(const float* __restrict__ x, int bg,
                                            int xoff, int enc, int i) {
    float Eur = 1.f, Eui = 0.f, Evr = 0.f, Evi = 0.f;
    #pragma unroll
    for (int j = 0; j < 4; j++) {
        float2 p0 = g_encphi[enc * 64 + 8 * i + 2 * j];
        float2 p1 = g_encphi[enc * 64 + 8 * i + 2 * j + 1];
        float xv = x[(size_t)bg * NXF + xoff + 4 * i + j];
        float sx, cx;
        sincosf(0.5f * xv, &sx, &cx);
        if ((j & 1) == 0) {
            su2_mul(Eur, Eui, Evr, Evi, p0.x, 0.f, p0.y, 0.f);   // RY(p0)
            su2_mul(Eur, Eui, Evr, Evi, cx, 0.f, 0.f, -sx);      // RX(x)
            su2_mul(Eur, Eui, Evr, Evi, p1.x, 0.f, p1.y, 0.f);   // RY(p1)
        } else {
            su2_mul(Eur, Eui, Evr, Evi, p0.x, 0.f, 0.f, -p0.y);  // RX(p0)
            su2_mul(Eur, Eui, Evr, Evi, cx, 0.f, sx, 0.f);       // RY(x)
            su2_mul(Eur, Eui, Evr, Evi, p1.x, 0.f, 0.f, -p1.y);  // RX(p1)
        }
    }
    return make_float4(Eur, Eui, Evr, Evi);
}

__device__ __forceinline__ void apply_gates(float2* sPsi, const float4* sE, int tid) {
    #pragma unroll
    for (int q = 0; q < 8; q++) {
        int p = 7 - q;
        int low = (1 << p) - 1;
        #pragma unroll
        for (int it = 0; it < (128 * NT) / 256; it++) {  // 16
            int task = tid + it * 256;
            int b = task & (NT - 1);
            int pr = task >> 5;
            int n0 = ((pr & ~low) << 1) | (pr & low);
            int n1 = n0 | (1 << p);
            float4 E = sE[q * NT + b];
            float2 a0 = sPsi[n0 * NTP + b];
            float2 a1 = sPsi[n1 * NTP + b];
            float2 b0, b1;
            b0.x = E.x * a0.x - E.y * a0.y - (E.z * a1.x + E.w * a1.y);
            b0.y = E.x * a0.y + E.y * a0.x - (E.z * a1.y - E.w * a1.x);
            b1.x = E.z * a0.x - E.w * a0.y + (E.x * a1.x + E.y * a1.y);
            b1.y = E.z * a0.y + E.w * a0.x + (E.x * a1.y - E.y * a1.x);
            sPsi[n0 * NTP + b] = b0;
            sPsi[n1 * NTP + b] = b1;
        }
        __syncthreads();
    }
}

// in-place complex GEMM using packed f32x2 FMAs:
//   sPsi[m][b] = sum_k AT[k][m] * sPsi[k][b]
// A-tile staged into shared pre-expanded as (a.r, a.i, -a.i, a.r) so each
// LDS.128 delivers both packed operands; global loads software-pipelined.
__device__ __forceinline__ void do_gemm(float2* sPsi, float4* sA4,
                                        const float2* __restrict__ AT,
                                        int tid, int lane, int warp) {
    ull acc[8][4];
    #pragma unroll
    for (int r = 0; r < 8; r++)
        #pragma unroll
        for (int j = 0; j < 4; j++) acc[r][j] = 0ull;

    float2 pre[8];
    #pragma unroll
    for (int r = 0; r < 8; r++) pre[r] = AT[tid + r * 256];   // kc = 0 prefetch

    for (int kc = 0; kc < 32; kc++) {
        __syncthreads();  // previous compute done reading sA4
        #pragma unroll
        for (int r = 0; r < 8; r++) {
            float2 v = pre[r];
            sA4[tid + r * 256] = make_float4(v.x, v.y, -v.y, v.x);
        }
        __syncthreads();
        if (kc + 1 < 32) {
            #pragma unroll
            for (int r = 0; r < 8; r++) pre[r] = AT[(kc + 1) * 2048 + tid + r * 256];
        }
        #pragma unroll
        for (int kk = 0; kk < 8; kk++) {
            int k = kc * 8 + kk;
            ull Br[4], Bi[4];
            #pragma unroll
            for (int j = 0; j < 4; j++) {
                float2 bv = sPsi[k * NTP + warp * 4 + j];
                Br[j] = pack2(bv.x, bv.x);
                Bi[j] = pack2(bv.y, bv.y);
            }
            #pragma unroll
            for (int r = 0; r < 8; r++) {
                ulonglong2 av = *reinterpret_cast<const ulonglong2*>(&sA4[kk * 256 + lane + 32 * r]);
                #pragma unroll
                for (int j = 0; j < 4; j++) {
                    ffma2(acc[r][j], av.x, Br[j]);   // (a.r,a.i) * (b.r,b.r)
                    ffma2(acc[r][j], av.y, Bi[j]);   // (-a.i,a.r) * (b.i,b.i)
                }
            }
        }
    }
    __syncthreads();  // all reads of sPsi done before overwrite
    #pragma unroll
    for (int r = 0; r < 8; r++)
        #pragma unroll
        for (int j = 0; j < 4; j++)
            *reinterpret_cast<ull*>(&sPsi[(lane + 32 * r) * NTP + warp * 4 + j]) = acc[r][j];
    __syncthreads();
}

__global__ void __launch_bounds__(256, 2) k_main(const float* __restrict__ x,
                                                 float* __restrict__ out) {
    extern __shared__ float smraw[];
    float2* sPsi = (float2*)smraw;              // NS * NTP         (67584 B)
    float4* sA4  = (float4*)(sPsi + NS * NTP);  // 8 * 256 float4   (32768 B)
    float4* sE   = sA4 + 8 * NS;                // 8 * NT float4    ( 4096 B)

    int tid = threadIdx.x;
    int lane = tid & 31, warp = tid >> 5;       // 8 warps
    int bbase = blockIdx.x * NT;

    // ---- E1 compose: tid -> (b = tid&31, i = tid>>5) ----
    {
        int b = tid & (NT - 1), i = tid >> 5;
        sE[i * NT + b] = compose_E(x, bbase + b, 0, 0, i);
    }
    // ---- init Psi = v0 (broadcast over batches) ----
    for (int idx = tid; idx < NS * NT; idx += 256) {
        int b = idx & (NT - 1), amp = idx >> 5;
        sPsi[amp * NTP + b] = g_v0[amp];
    }
    __syncthreads();

    apply_gates(sPsi, sE, tid);                 // encode 1 (CZ folded into U2')
    do_gemm(sPsi, sA4, g_U2T, tid, lane, warp);

    // ---- E2 compose ----
    {
        int b = tid & (NT - 1), i = tid >> 5;
        sE[i * NT + b] = compose_E(x, bbase + b, 32, 1, i);
    }
    __syncthreads();

    apply_gates(sPsi, sE, tid);                 // encode 2 (CZ folded into U3')
    do_gemm(sPsi, sA4, g_U3T, tid, lane, warp);

    // ---- measurement: warp w handles batches w*4..w*4+3 ----
    for (int j = 0; j < 4; j++) {
        int b = warp * 4 + j;
        float sums[8];
        #pragma unroll
        for (int k = 0; k < 8; k++) sums[k] = 0.f;
        #pragma unroll
        for (int r = 0; r < 8; r++) {
            int m = lane + 32 * r;
            float2 ps = sPsi[m * NTP + b];
            float p2 = ps.x * ps.x + ps.y * ps.y;
            sums[4] += (m & 128) ? -p2 : p2;   // Z q0
            sums[5] += (m & 64)  ? -p2 : p2;   // Z q1
            sums[6] += (m & 32)  ? -p2 : p2;   // Z q2
            sums[7] += (m & 16)  ? -p2 : p2;   // Z q3
            float2 q0 = sPsi[(m ^ 128) * NTP + b];
            sums[0] += ps.x * q0.x + ps.y * q0.y;   // X q0
            float2 q1 = sPsi[(m ^ 64) * NTP + b];
            sums[1] += ps.x * q1.x + ps.y * q1.y;   // X q1
            float2 q2 = sPsi[(m ^ 32) * NTP + b];
            sums[2] += ps.x * q2.x + ps.y * q2.y;   // X q2
            float2 q3 = sPsi[(m ^ 16) * NTP + b];
            sums[3] += ps.x * q3.x + ps.y * q3.y;   // X q3
        }
        #pragma unroll
        for (int off = 16; off; off >>= 1) {
            #pragma unroll
            for (int k = 0; k < 8; k++)
                sums[k] += __shfl_xor_sync(0xffffffffu, sums[k], off);
        }
        if (lane < 8) out[(size_t)(bbase + b) * 8 + lane] = sums[lane];
    }
}

// ---------------- launch ----------------
extern "C" void kernel_launch(void* const* d_in, const int* in_sizes, int n_in,
                              void* d_out, int out_size) {
    const float* x   = (const float*)d_in[0];
    const float* phi = (const float*)d_in[1];
    float* out = (float*)d_out;

    const size_t smem = (size_t)(NS * NTP) * sizeof(float2)   // 67584
                      + (size_t)(8 * NS) * sizeof(float4)     // 32768
                      + (size_t)(8 * NT) * sizeof(float4);    //  4096
    cudaFuncSetAttribute(k_main, cudaFuncAttributeMaxDynamicSharedMemorySize, (int)smem);

    k_tables<<<1, 256>>>(phi);
    k_build<<<513, 128>>>();
    k_main<<<NBLK, 256, smem>>>(x, out);
}